// round 1
// baseline (speedup 1.0000x reference)
#include <cuda_runtime.h>

// dynoNet G-block on GB300.
// Problem: y_io[t] = sum_k b_iok u_i[t-k] - sum_k a_iok y_io[t-1-k]
//          out[b,t,o] = sum_i y_io[t]
// Shapes: inputs [128,4096,8] f32, numerator [8,8,3] f32, denominator [8,8,3] f32,
//         output [128,4096,8] f32.
//
// Strategy: |a| <= 0.01 => IIR spectral radius < 0.25 => state influence decays
// ~0.25^t. Split T into chunks of 128 with 24 warm-up steps run from zero state
// (discarded); error contribution < 1e-14 relative. One thread per (b,o,chunk)
// handles all 8 input channels i in registers: in-thread reduction over i,
// vectorized u loads, coalesced output stores.

#define B_SZ   128
#define T_LEN  4096
#define I_CH   8
#define O_CH   8
#define NB_    3
#define NA_    3
#define CHUNK  128
#define WARM   24
#define NCHUNK (T_LEN / CHUNK)          // 32
#define NTHREADS (B_SZ * O_CH * NCHUNK) // 32768

__global__ __launch_bounds__(128)
void dyno_gblock_kernel(const float* __restrict__ u,
                        const float* __restrict__ num,
                        const float* __restrict__ den,
                        float* __restrict__ out)
{
    const int tid   = blockIdx.x * blockDim.x + threadIdx.x;
    const int o     = tid & (O_CH - 1);          // 8 o-lanes contiguous -> coalesced STG
    const int b     = (tid >> 3) & (B_SZ - 1);   // 4 b per warp -> u broadcast in groups of 8
    const int chunk = tid >> 10;                 // uniform within a warp

    // ---- coefficients for this o, all i (negate a so the IIR is pure FMA) ----
    float cb0[I_CH], cb1[I_CH], cb2[I_CH];
    float ca0[I_CH], ca1[I_CH], ca2[I_CH];
#pragma unroll
    for (int i = 0; i < I_CH; ++i) {
        const float* nb = num + (i * O_CH + o) * NB_;
        cb0[i] = nb[0]; cb1[i] = nb[1]; cb2[i] = nb[2];
        const float* na = den + (i * O_CH + o) * NA_;
        ca0[i] = -na[0]; ca1[i] = -na[1]; ca2[i] = -na[2];
    }

    // ---- state: y history (3 deep) and u history (2 deep) per input channel ----
    float y1[I_CH], y2[I_CH], y3[I_CH], u1[I_CH], u2[I_CH];
#pragma unroll
    for (int i = 0; i < I_CH; ++i) {
        y1[i] = y2[i] = y3[i] = 0.f;
        u1[i] = u2[i] = 0.f;
    }

    const int tStart = chunk * CHUNK;
    int tBeg = tStart - WARM;
    if (tBeg < 0) tBeg = 0;                      // chunk 0: exact zero initial state

    const float4* __restrict__ ubase =
        reinterpret_cast<const float4*>(u + (size_t)b * T_LEN * I_CH);
    float* __restrict__ obase = out + (size_t)b * T_LEN * O_CH + o;

    // ---- warm-up: run recursion, discard outputs ----
    for (int t = tBeg; t < tStart; ++t) {
        const float4 ua = __ldg(ubase + 2 * t);
        const float4 ub = __ldg(ubase + 2 * t + 1);
        const float uc[I_CH] = {ua.x, ua.y, ua.z, ua.w, ub.x, ub.y, ub.z, ub.w};
#pragma unroll
        for (int i = 0; i < I_CH; ++i) {
            float x = fmaf(cb0[i], uc[i], fmaf(cb1[i], u1[i], cb2[i] * u2[i]));
            // chain ordered so only the ca0*y1 fma is on the t->t+1 critical path
            float y = fmaf(ca0[i], y1[i], fmaf(ca1[i], y2[i], fmaf(ca2[i], y3[i], x)));
            u2[i] = u1[i]; u1[i] = uc[i];
            y3[i] = y2[i]; y2[i] = y1[i]; y1[i] = y;
        }
    }

    // ---- main: 128 steps, store sum over i each step ----
#pragma unroll 6
    for (int t = tStart; t < tStart + CHUNK; ++t) {
        const float4 ua = __ldg(ubase + 2 * t);
        const float4 ub = __ldg(ubase + 2 * t + 1);
        const float uc[I_CH] = {ua.x, ua.y, ua.z, ua.w, ub.x, ub.y, ub.z, ub.w};
#pragma unroll
        for (int i = 0; i < I_CH; ++i) {
            float x = fmaf(cb0[i], uc[i], fmaf(cb1[i], u1[i], cb2[i] * u2[i]));
            float y = fmaf(ca0[i], y1[i], fmaf(ca1[i], y2[i], fmaf(ca2[i], y3[i], x)));
            u2[i] = u1[i]; u1[i] = uc[i];
            y3[i] = y2[i]; y2[i] = y1[i]; y1[i] = y;
        }
        const float s = ((y1[0] + y1[1]) + (y1[2] + y1[3]))
                      + ((y1[4] + y1[5]) + (y1[6] + y1[7]));
        obase[(size_t)t * O_CH] = s;
    }
}

extern "C" void kernel_launch(void* const* d_in, const int* in_sizes, int n_in,
                              void* d_out, int out_size)
{
    const float* u   = (const float*)d_in[0];  // inputs      [128,4096,8]
    const float* num = (const float*)d_in[1];  // numerator   [8,8,3]
    const float* den = (const float*)d_in[2];  // denominator [8,8,3]
    float* out = (float*)d_out;                // output      [128,4096,8]

    dyno_gblock_kernel<<<NTHREADS / 128, 128>>>(u, num, den, out);
}

// round 2
// speedup vs baseline: 1.0880x; 1.0880x over previous
#include <cuda_runtime.h>

// dynoNet G-block on GB300 — round 2: packed f32x2 math + 2x parallelism.
//
// y_io[t] = sum_k b_iok u_i[t-k] - sum_k a_iok y_io[t-1-k];  out[b,t,o] = sum_i y_io[t]
// inputs [128,4096,8] f32, numerator [8,8,3], denominator [8,8,3], out [128,4096,8].
//
// |a| <= 0.01 => IIR spectral radius ~0.233 => 16 warm-up steps reduce unknown-state
// influence to ~7e-11 relative. T split into 64 chunks of 64. One thread per
// (b,o,chunk); the 8 input channels live in 4 packed f32x2 lanes (channels are
// adjacent in memory, so ulonglong2 loads deliver pre-packed operands).

#define B_SZ   128
#define T_LEN  4096
#define I_CH   8
#define O_CH   8
#define CHUNK  64
#define WARM   16
#define NCHUNK (T_LEN / CHUNK)            // 64
#define NTHREADS (B_SZ * O_CH * NCHUNK)   // 65536

typedef unsigned long long u64;

__device__ __forceinline__ u64 f2_fma(u64 a, u64 b, u64 c) {
    u64 d; asm("fma.rn.f32x2 %0,%1,%2,%3;" : "=l"(d) : "l"(a), "l"(b), "l"(c)); return d;
}
__device__ __forceinline__ u64 f2_mul(u64 a, u64 b) {
    u64 d; asm("mul.rn.f32x2 %0,%1,%2;" : "=l"(d) : "l"(a), "l"(b)); return d;
}
__device__ __forceinline__ u64 f2_add(u64 a, u64 b) {
    u64 d; asm("add.rn.f32x2 %0,%1,%2;" : "=l"(d) : "l"(a), "l"(b)); return d;
}
__device__ __forceinline__ u64 f2_pack(float lo, float hi) {
    u64 d; asm("mov.b64 %0,{%1,%2};" : "=l"(d) : "f"(lo), "f"(hi)); return d;
}
__device__ __forceinline__ float f2_hsum(u64 a) {
    float lo, hi; asm("mov.b64 {%0,%1},%2;" : "=f"(lo), "=f"(hi) : "l"(a)); return lo + hi;
}

__global__ __launch_bounds__(128)
void dyno_gblock_kernel(const float* __restrict__ u,
                        const float* __restrict__ num,
                        const float* __restrict__ den,
                        float* __restrict__ out)
{
    const int tid   = blockIdx.x * blockDim.x + threadIdx.x;
    const int o     = tid & (O_CH - 1);         // 8 o-lanes contiguous -> coalesced STG
    const int b     = (tid >> 3) & (B_SZ - 1);  // 4 b per warp; u row broadcast per 8 lanes
    const int chunk = tid >> 10;                // uniform within a warp

    // ---- packed coefficients: lane p holds channels (2p, 2p+1) for this o ----
    u64 cb0[4], cb1[4], cb2[4], ca0[4], ca1[4], ca2[4];
#pragma unroll
    for (int p = 0; p < 4; ++p) {
        const int i0 = 2 * p, i1 = 2 * p + 1;
        const float* n0 = num + (i0 * O_CH + o) * 3;
        const float* n1 = num + (i1 * O_CH + o) * 3;
        cb0[p] = f2_pack(n0[0], n1[0]);
        cb1[p] = f2_pack(n0[1], n1[1]);
        cb2[p] = f2_pack(n0[2], n1[2]);
        const float* d0 = den + (i0 * O_CH + o) * 3;
        const float* d1 = den + (i1 * O_CH + o) * 3;
        ca0[p] = f2_pack(-d0[0], -d1[0]);
        ca1[p] = f2_pack(-d0[1], -d1[1]);
        ca2[p] = f2_pack(-d0[2], -d1[2]);
    }

    // ---- packed state: y history (3) and u history (2); 0ull == packed (0f,0f) ----
    u64 y1[4], y2[4], y3[4], u1[4], u2[4];
#pragma unroll
    for (int p = 0; p < 4; ++p) { y1[p] = y2[p] = y3[p] = 0ull; u1[p] = u2[p] = 0ull; }

    const int tStart = chunk * CHUNK;
    int tBeg = tStart - WARM;
    if (tBeg < 0) tBeg = 0;                     // chunk 0 starts from the true zero state

    const ulonglong2* __restrict__ ubase =
        reinterpret_cast<const ulonglong2*>(u + (size_t)b * T_LEN * I_CH);
    float* __restrict__ obase = out + (size_t)b * T_LEN * O_CH + o;

    // ---- warm-up (outputs discarded) ----
#pragma unroll 4
    for (int t = tBeg; t < tStart; ++t) {
        const ulonglong2 A = __ldg(ubase + 2 * t);
        const ulonglong2 Bq = __ldg(ubase + 2 * t + 1);
        const u64 uc[4] = {A.x, A.y, Bq.x, Bq.y};
#pragma unroll
        for (int p = 0; p < 4; ++p) {
            u64 x = f2_fma(cb1[p], u1[p], f2_mul(cb2[p], u2[p]));
            x = f2_fma(cb0[p], uc[p], x);
            x = f2_fma(ca2[p], y3[p], x);
            x = f2_fma(ca1[p], y2[p], x);
            u64 y = f2_fma(ca0[p], y1[p], x);   // only op on the t->t+1 critical path
            u2[p] = u1[p]; u1[p] = uc[p];
            y3[p] = y2[p]; y2[p] = y1[p]; y1[p] = y;
        }
    }

    // ---- main: 64 steps, store sum over channels each step ----
#pragma unroll 6
    for (int t = tStart; t < tStart + CHUNK; ++t) {
        const ulonglong2 A = __ldg(ubase + 2 * t);
        const ulonglong2 Bq = __ldg(ubase + 2 * t + 1);
        const u64 uc[4] = {A.x, A.y, Bq.x, Bq.y};
#pragma unroll
        for (int p = 0; p < 4; ++p) {
            u64 x = f2_fma(cb1[p], u1[p], f2_mul(cb2[p], u2[p]));
            x = f2_fma(cb0[p], uc[p], x);
            x = f2_fma(ca2[p], y3[p], x);
            x = f2_fma(ca1[p], y2[p], x);
            u64 y = f2_fma(ca0[p], y1[p], x);
            u2[p] = u1[p]; u1[p] = uc[p];
            y3[p] = y2[p]; y2[p] = y1[p]; y1[p] = y;
        }
        const u64 s = f2_add(f2_add(y1[0], y1[1]), f2_add(y1[2], y1[3]));
        obase[(size_t)t * O_CH] = f2_hsum(s);
    }
}

extern "C" void kernel_launch(void* const* d_in, const int* in_sizes, int n_in,
                              void* d_out, int out_size)
{
    const float* u   = (const float*)d_in[0];  // inputs      [128,4096,8]
    const float* num = (const float*)d_in[1];  // numerator   [8,8,3]
    const float* den = (const float*)d_in[2];  // denominator [8,8,3]
    float* out = (float*)d_out;                // output      [128,4096,8]

    dyno_gblock_kernel<<<NTHREADS / 128, 128>>>(u, num, den, out);
}

// round 3
// speedup vs baseline: 1.1931x; 1.0965x over previous
#include <cuda_runtime.h>

// dynoNet G-block on GB300 — round 3: split channels across thread pairs to
// double occupancy (the R2 profile showed latency-bound at 14.9% occupancy).
//
// y_io[t] = sum_k b_iok u_i[t-k] - sum_k a_iok y_io[t-1-k];  out[b,t,o] = sum_i y_io[t]
// inputs [128,4096,8] f32, numerator [8,8,3], denominator [8,8,3], out [128,4096,8].
//
// |a| <= 0.01 => IIR spectral radius ~0.233 => 16 warm-up steps reduce unknown-state
// influence to ~7e-11 relative. T split into 64 chunks of 64.
//
// Thread layout: tid bits = [chunk | b(7) | half(1) | o(3)].
//   Each thread: one (b,o,chunk), channels [4*half, 4*half+4) in 2 f32x2 lanes.
//   Partner (other 4 channels) is lane xor 8 -> one float shfl per step.
//   Lane 0-7 / 8-15 of a warp load the same 16B u half-row (broadcast).

#define B_SZ   128
#define T_LEN  4096
#define I_CH   8
#define O_CH   8
#define CHUNK  64
#define WARM   16
#define NCHUNK (T_LEN / CHUNK)                 // 64
#define NTHREADS (B_SZ * O_CH * 2 * NCHUNK)    // 131072

typedef unsigned long long u64;

__device__ __forceinline__ u64 f2_fma(u64 a, u64 b, u64 c) {
    u64 d; asm("fma.rn.f32x2 %0,%1,%2,%3;" : "=l"(d) : "l"(a), "l"(b), "l"(c)); return d;
}
__device__ __forceinline__ u64 f2_mul(u64 a, u64 b) {
    u64 d; asm("mul.rn.f32x2 %0,%1,%2;" : "=l"(d) : "l"(a), "l"(b)); return d;
}
__device__ __forceinline__ u64 f2_add(u64 a, u64 b) {
    u64 d; asm("add.rn.f32x2 %0,%1,%2;" : "=l"(d) : "l"(a), "l"(b)); return d;
}
__device__ __forceinline__ u64 f2_pack(float lo, float hi) {
    u64 d; asm("mov.b64 %0,{%1,%2};" : "=l"(d) : "f"(lo), "f"(hi)); return d;
}
__device__ __forceinline__ float f2_hsum(u64 a) {
    float lo, hi; asm("mov.b64 {%0,%1},%2;" : "=f"(lo), "=f"(hi) : "l"(a)); return lo + hi;
}

__global__ __launch_bounds__(128)
void dyno_gblock_kernel(const float* __restrict__ u,
                        const float* __restrict__ num,
                        const float* __restrict__ den,
                        float* __restrict__ out)
{
    const int tid   = blockIdx.x * blockDim.x + threadIdx.x;
    const int o     = tid & (O_CH - 1);          // 8 o-lanes contiguous -> coalesced STG
    const int half  = (tid >> 3) & 1;            // which 4 input channels
    const int b     = (tid >> 4) & (B_SZ - 1);   // 2 b per warp
    const int chunk = tid >> 11;                 // uniform within a warp

    // ---- packed coefficients: lane p holds channels (4*half+2p, 4*half+2p+1) ----
    u64 cb0[2], cb1[2], cb2[2], ca0[2], ca1[2], ca2[2];
#pragma unroll
    for (int p = 0; p < 2; ++p) {
        const int i0 = 4 * half + 2 * p, i1 = i0 + 1;
        const float* n0 = num + (i0 * O_CH + o) * 3;
        const float* n1 = num + (i1 * O_CH + o) * 3;
        cb0[p] = f2_pack(n0[0], n1[0]);
        cb1[p] = f2_pack(n0[1], n1[1]);
        cb2[p] = f2_pack(n0[2], n1[2]);
        const float* d0 = den + (i0 * O_CH + o) * 3;
        const float* d1 = den + (i1 * O_CH + o) * 3;
        ca0[p] = f2_pack(-d0[0], -d1[0]);
        ca1[p] = f2_pack(-d0[1], -d1[1]);
        ca2[p] = f2_pack(-d0[2], -d1[2]);
    }

    // ---- packed state: y history (3) and u history (2); 0ull == (0f,0f) ----
    u64 y1[2], y2[2], y3[2], u1[2], u2[2];
#pragma unroll
    for (int p = 0; p < 2; ++p) { y1[p] = y2[p] = y3[p] = 0ull; u1[p] = u2[p] = 0ull; }

    const int tStart = chunk * CHUNK;
    int tBeg = tStart - WARM;
    if (tBeg < 0) tBeg = 0;                      // chunk 0 starts from the true zero state

    // this thread's 16B half-row: u[b, t, 4*half .. 4*half+3]
    const ulonglong2* __restrict__ ubase =
        reinterpret_cast<const ulonglong2*>(u + (size_t)b * T_LEN * I_CH) + half;
    float* __restrict__ obase = out + (size_t)b * T_LEN * O_CH + o;

    // ---- warm-up (outputs discarded) ----
#pragma unroll 4
    for (int t = tBeg; t < tStart; ++t) {
        const ulonglong2 A = __ldg(ubase + 2 * t);
        const u64 uc[2] = {A.x, A.y};
#pragma unroll
        for (int p = 0; p < 2; ++p) {
            u64 x = f2_fma(cb1[p], u1[p], f2_mul(cb2[p], u2[p]));
            x = f2_fma(cb0[p], uc[p], x);
            x = f2_fma(ca2[p], y3[p], x);
            x = f2_fma(ca1[p], y2[p], x);
            u64 y = f2_fma(ca0[p], y1[p], x);    // only op on the t->t+1 critical path
            u2[p] = u1[p]; u1[p] = uc[p];
            y3[p] = y2[p]; y2[p] = y1[p]; y1[p] = y;
        }
    }

    // ---- main: 64 steps; pair-sum via shfl, half 0 stores ----
#pragma unroll 8
    for (int t = tStart; t < tStart + CHUNK; ++t) {
        const ulonglong2 A = __ldg(ubase + 2 * t);
        const u64 uc[2] = {A.x, A.y};
#pragma unroll
        for (int p = 0; p < 2; ++p) {
            u64 x = f2_fma(cb1[p], u1[p], f2_mul(cb2[p], u2[p]));
            x = f2_fma(cb0[p], uc[p], x);
            x = f2_fma(ca2[p], y3[p], x);
            x = f2_fma(ca1[p], y2[p], x);
            u64 y = f2_fma(ca0[p], y1[p], x);
            u2[p] = u1[p]; u1[p] = uc[p];
            y3[p] = y2[p]; y2[p] = y1[p]; y1[p] = y;
        }
        const float s     = f2_hsum(f2_add(y1[0], y1[1]));          // 4 channels
        const float other = __shfl_xor_sync(0xffffffffu, s, 8);     // partner's 4
        if (half == 0)
            obase[(size_t)t * O_CH] = s + other;
    }
}

extern "C" void kernel_launch(void* const* d_in, const int* in_sizes, int n_in,
                              void* d_out, int out_size)
{
    const float* u   = (const float*)d_in[0];  // inputs      [128,4096,8]
    const float* num = (const float*)d_in[1];  // numerator   [8,8,3]
    const float* den = (const float*)d_in[2];  // denominator [8,8,3]
    float* out = (float*)d_out;                // output      [128,4096,8]

    dyno_gblock_kernel<<<NTHREADS / 128, 128>>>(u, num, den, out);
}